// round 1
// baseline (speedup 1.0000x reference)
#include <cuda_runtime.h>
#include <cuda_bf16.h>
#include <cstdint>

// Problem shapes (Attention_18631568130094): B=4, Sq=2048, Sk=2048, D=1024
// Inputs: d_in[0]=query fp32 [4,2048,1,1024], d_in[1]=key fp32 [4,1,2048,1024],
//         d_in[2]=mask int32 [4,2048]
// Output: fp32 [4,2048,2048]

#define B_  4
#define SQ  2048
#define SK  2048
#define DD  1024
#define NEGV -1000000000.0f

// scratch for inverse norms (no cudaMalloc allowed)
__device__ float g_inv_qn[B_ * SQ];
__device__ float g_inv_kn[B_ * SK];

// ---------------------------------------------------------------------------
// Kernel 1: row L2 norms -> 1/max(norm, 1e-8). One block per row.
// rows [0, 8192) = query rows, rows [8192, 16384) = key rows.
// ---------------------------------------------------------------------------
__global__ __launch_bounds__(256) void norms_kernel(const float* __restrict__ q,
                                                    const float* __restrict__ k) {
    int row = blockIdx.x;
    const float* src;
    float* dst;
    if (row < B_ * SQ) {
        src = q + (size_t)row * DD;
        dst = &g_inv_qn[row];
    } else {
        int r = row - B_ * SQ;
        src = k + (size_t)r * DD;
        dst = &g_inv_kn[r];
    }

    float s = 0.0f;
    // 1024 floats / 256 threads = 4 each; vectorized float4
    const float4* src4 = (const float4*)src;
    float4 v = src4[threadIdx.x];  // 256 * 4 = 1024 floats exactly
    s = v.x * v.x + v.y * v.y + v.z * v.z + v.w * v.w;

    // warp reduce
    #pragma unroll
    for (int off = 16; off > 0; off >>= 1)
        s += __shfl_xor_sync(0xFFFFFFFFu, s, off);

    __shared__ float red[8];
    int wid = threadIdx.x >> 5;
    int lid = threadIdx.x & 31;
    if (lid == 0) red[wid] = s;
    __syncthreads();
    if (threadIdx.x == 0) {
        float t = 0.0f;
        #pragma unroll
        for (int i = 0; i < 8; i++) t += red[i];
        float n = sqrtf(t);
        n = fmaxf(n, 1e-8f);
        *dst = 1.0f / n;
    }
}

// ---------------------------------------------------------------------------
// Kernel 2: per-batch GEMM C = Q * K^T with fused cosine normalization + mask.
// 128x128 block tile, BK=16, 256 threads, 8x8 per thread.
// Inner loop uses packed fma.rn.f32x2 (2 MACs / issue slot on sm_103a).
// ---------------------------------------------------------------------------
#define BM 128
#define BN 128
#define BK 16
#define PAD 4

__global__ __launch_bounds__(256, 2) void gemm_kernel(const float* __restrict__ Q,
                                                      const float* __restrict__ K,
                                                      const int* __restrict__ mask,
                                                      float* __restrict__ out) {
    const int b  = blockIdx.z;
    const int bm = blockIdx.y * BM;
    const int bn = blockIdx.x * BN;

    const float* Qb = Q + (size_t)b * SQ * DD;
    const float* Kb = K + (size_t)b * SK * DD;

    __shared__ float As[BK][BM + PAD];   // [k][m]
    __shared__ float Bs[BK][BN + PAD];   // [k][n]  (BN+PAD=132 floats -> 528B rows, 16B aligned)

    const int tid = threadIdx.x;
    const int tx  = tid & 15;   // n-group
    const int ty  = tid >> 4;   // m-group

    // packed accumulators: acc[i][j] holds (n = tx*8 + 2j, tx*8 + 2j+1) for m-row i
    unsigned long long acc[8][4];
    #pragma unroll
    for (int i = 0; i < 8; i++)
        #pragma unroll
        for (int j = 0; j < 4; j++) acc[i][j] = 0ull;  // bitwise 0 == {0.0f, 0.0f}

    // global load mapping: each thread loads 2 float4 from Q and 2 from K per tile
    const int lrow = tid >> 2;        // 0..63
    const int lcol = (tid & 3) * 4;   // k offset within tile (float4 granularity)

    for (int k0 = 0; k0 < DD; k0 += BK) {
        #pragma unroll
        for (int r = 0; r < 2; r++) {
            int m = lrow + r * 64;
            float4 va = *(const float4*)&Qb[(size_t)(bm + m) * DD + k0 + lcol];
            As[lcol + 0][m] = va.x;
            As[lcol + 1][m] = va.y;
            As[lcol + 2][m] = va.z;
            As[lcol + 3][m] = va.w;
            float4 vb = *(const float4*)&Kb[(size_t)(bn + m) * DD + k0 + lcol];
            Bs[lcol + 0][m] = vb.x;
            Bs[lcol + 1][m] = vb.y;
            Bs[lcol + 2][m] = vb.z;
            Bs[lcol + 3][m] = vb.w;
        }
        __syncthreads();

        #pragma unroll
        for (int kk = 0; kk < BK; kk++) {
            // B operands: 8 floats = 4 packed pairs (8B-aligned: tx*8 floats = 32B)
            unsigned long long bp[4];
            const unsigned long long* brow =
                (const unsigned long long*)&Bs[kk][tx * 8];
            #pragma unroll
            for (int j = 0; j < 4; j++) bp[j] = brow[j];

            float a[8];
            #pragma unroll
            for (int i = 0; i < 8; i++) a[i] = As[kk][ty * 8 + i];

            #pragma unroll
            for (int i = 0; i < 8; i++) {
                unsigned long long ap;
                asm("mov.b64 %0, {%1, %1};" : "=l"(ap) : "f"(a[i]));
                #pragma unroll
                for (int j = 0; j < 4; j++) {
                    asm("fma.rn.f32x2 %0, %1, %2, %0;"
                        : "+l"(acc[i][j])
                        : "l"(ap), "l"(bp[j]));
                }
            }
        }
        __syncthreads();
    }

    // ---- epilogue: cosine normalization + mask ----
    const int nbase = bn + tx * 8;
    float invk[8];
    int   mv[8];
    #pragma unroll
    for (int j = 0; j < 8; j++) {
        invk[j] = g_inv_kn[b * SK + nbase + j];
        mv[j]   = mask[b * SK + nbase + j];
    }

    #pragma unroll
    for (int i = 0; i < 8; i++) {
        const int m = bm + ty * 8 + i;
        const float invq = g_inv_qn[b * SQ + m];
        float res[8];
        #pragma unroll
        for (int j = 0; j < 4; j++) {
            float lo, hi;
            asm("mov.b64 {%0, %1}, %2;" : "=f"(lo), "=f"(hi) : "l"(acc[i][j]));
            res[2 * j]     = lo;
            res[2 * j + 1] = hi;
        }
        float o[8];
        #pragma unroll
        for (int j = 0; j < 8; j++)
            o[j] = (mv[j] != 0) ? res[j] * invq * invk[j] : NEGV;

        float* orow = out + ((size_t)b * SQ + m) * SK + nbase;
        *(float4*)(orow)     = make_float4(o[0], o[1], o[2], o[3]);
        *(float4*)(orow + 4) = make_float4(o[4], o[5], o[6], o[7]);
    }
}

// ---------------------------------------------------------------------------
extern "C" void kernel_launch(void* const* d_in, const int* in_sizes, int n_in,
                              void* d_out, int out_size) {
    const float* q    = (const float*)d_in[0];
    const float* k    = (const float*)d_in[1];
    const int*   mask = (const int*)d_in[2];
    float*       out  = (float*)d_out;

    norms_kernel<<<B_ * SQ + B_ * SK, 256>>>(q, k);

    dim3 grid(SK / BN, SQ / BM, B_);
    gemm_kernel<<<grid, 256>>>(q, k, mask, out);
}

// round 3
// speedup vs baseline: 4.8693x; 4.8693x over previous
#include <cuda_runtime.h>
#include <cuda_bf16.h>
#include <cstdint>

// Attention_18631568130094: B=4, Sq=2048, Sk=2048, D=1024
// out[b,q,k] = mask[b,k] ? (Q[b,q]·K[b,k])/(|Q[b,q]||K[b,k]|) : -1e9

#define B_  4
#define SQ  2048
#define SK  2048
#define DD  1024
#define NEGV -1000000000.0f

// ---------------- device scratch (no cudaMalloc allowed) -------------------
__device__ float g_inv_qn[B_ * SQ];
__device__ float g_inv_kn[B_ * SK];
__device__ __nv_bfloat16 g_qb[(size_t)B_ * SQ * DD];
__device__ __nv_bfloat16 g_kb[(size_t)B_ * SK * DD];

// ---------------- helpers --------------------------------------------------
__device__ __forceinline__ uint32_t smem_u32(const void* p) {
    uint32_t a;
    asm("{ .reg .u64 t; cvta.to.shared.u64 t, %1; cvt.u32.u64 %0, t; }"
        : "=r"(a) : "l"(p));
    return a;
}
__device__ __forceinline__ void cp_async16(uint32_t s, const void* g) {
    asm volatile("cp.async.cg.shared.global [%0], [%1], 16;" :: "r"(s), "l"(g));
}
#define CP_COMMIT() asm volatile("cp.async.commit_group;" ::: "memory")
#define CP_WAIT(n)  asm volatile("cp.async.wait_group %0;" :: "n"(n) : "memory")

#define LDSM_X4(r0, r1, r2, r3, addr) \
    asm volatile("ldmatrix.sync.aligned.m8n8.x4.shared.b16 {%0,%1,%2,%3}, [%4];" \
        : "=r"(r0), "=r"(r1), "=r"(r2), "=r"(r3) : "r"(addr))

#define MMA16816(d, a, bfr) \
    asm volatile("mma.sync.aligned.m16n8k16.row.col.f32.bf16.bf16.f32 " \
        "{%0,%1,%2,%3}, {%4,%5,%6,%7}, {%8,%9}, {%0,%1,%2,%3};" \
        : "+f"((d)[0]), "+f"((d)[1]), "+f"((d)[2]), "+f"((d)[3]) \
        : "r"((a)[0]), "r"((a)[1]), "r"((a)[2]), "r"((a)[3]), \
          "r"((bfr)[0]), "r"((bfr)[1]))

// ---------------------------------------------------------------------------
// Kernel 1: fused row-norm + bf16 conversion. One block (256 thr) per row.
// ---------------------------------------------------------------------------
__global__ __launch_bounds__(256) void prep_kernel(const float* __restrict__ q,
                                                   const float* __restrict__ k) {
    int row = blockIdx.x;
    const float* src;
    __nv_bfloat16* dstb;
    float* dstn;
    if (row < B_ * SQ) {
        src = q + (size_t)row * DD;
        dstb = g_qb + (size_t)row * DD;
        dstn = &g_inv_qn[row];
    } else {
        int r = row - B_ * SQ;
        src = k + (size_t)r * DD;
        dstb = g_kb + (size_t)r * DD;
        dstn = &g_inv_kn[r];
    }
    float4 v = ((const float4*)src)[threadIdx.x];  // 256*4 = 1024 exactly

    __nv_bfloat162 b0 = __floats2bfloat162_rn(v.x, v.y);
    __nv_bfloat162 b1 = __floats2bfloat162_rn(v.z, v.w);
    uint2 pk;
    pk.x = *(uint32_t*)&b0;
    pk.y = *(uint32_t*)&b1;
    ((uint2*)dstb)[threadIdx.x] = pk;

    float s = v.x * v.x + v.y * v.y + v.z * v.z + v.w * v.w;
    #pragma unroll
    for (int off = 16; off > 0; off >>= 1)
        s += __shfl_xor_sync(0xFFFFFFFFu, s, off);

    __shared__ float red[8];
    if ((threadIdx.x & 31) == 0) red[threadIdx.x >> 5] = s;
    __syncthreads();
    if (threadIdx.x == 0) {
        float t = 0.0f;
        #pragma unroll
        for (int i = 0; i < 8; i++) t += red[i];
        *dstn = 1.0f / fmaxf(sqrtf(t), 1e-8f);
    }
}

// ---------------------------------------------------------------------------
// Kernel 2: bf16 mma.sync GEMM. CTA tile 128x128, BK=64, 3-stage cp.async.
// 8 warps, warp tile 32(m) x 64(n); mma m16n8k16.
// SMEM stage: A 16KB + B 16KB = 32KB; rows are 128B, xor-swizzled by (row&7).
// ---------------------------------------------------------------------------
#define STAGES 3
#define NK 16                  // 1024 / 64
#define STAGE_BYTES 32768
#define SMEM_TOTAL (STAGES * STAGE_BYTES)

__global__ __launch_bounds__(256) void gemm_mma_kernel(const int* __restrict__ mask,
                                                       float* __restrict__ out) {
    extern __shared__ char smem[];
    const int tid = threadIdx.x;
    const int b = blockIdx.z;
    const int bm = blockIdx.y * 128;
    const int bn = blockIdx.x * 128;

    __shared__ float s_kk[128];
    if (tid < 128) {
        int n = bn + tid;
        s_kk[tid] = mask[b * SK + n] ? g_inv_kn[b * SK + n] : 0.0f;
    }

    const __nv_bfloat16* Qb = g_qb + ((size_t)b * SQ + bm) * DD;
    const __nv_bfloat16* Kb = g_kb + ((size_t)b * SK + bn) * DD;

    // load mapping: thread t covers row t/2, chunks (t%2)*4 .. +3 (16B chunks)
    const int lr = tid >> 1;
    const int lc0 = (tid & 1) * 4;
    const uint32_t sb = smem_u32(smem);

    #define LOAD_TILE(slot, it) do {                                           \
        uint32_t sA = sb + (slot) * STAGE_BYTES;                               \
        uint32_t sB = sA + 16384;                                              \
        const __nv_bfloat16* gA = Qb + (size_t)lr * DD + (it) * 64 + lc0 * 8;  \
        const __nv_bfloat16* gB = Kb + (size_t)lr * DD + (it) * 64 + lc0 * 8;  \
        _Pragma("unroll")                                                      \
        for (int i = 0; i < 4; i++) {                                          \
            int c = lc0 + i;                                                   \
            uint32_t off = lr * 128 + ((c ^ (lr & 7)) * 16);                   \
            cp_async16(sA + off, gA + i * 8);                                  \
            cp_async16(sB + off, gB + i * 8);                                  \
        }                                                                      \
    } while (0)

    float acc[2][8][4];
    #pragma unroll
    for (int mf = 0; mf < 2; mf++)
        #pragma unroll
        for (int nf = 0; nf < 8; nf++)
            #pragma unroll
            for (int r = 0; r < 4; r++) acc[mf][nf][r] = 0.0f;

    const int w = tid >> 5, l = tid & 31;
    const int wm = (w & 3) * 32;     // warp m offset
    const int wn = (w >> 2) * 64;    // warp n offset

    LOAD_TILE(0, 0);
    CP_COMMIT();
    LOAD_TILE(1, 1);
    CP_COMMIT();

    for (int it = 0; it < NK; it++) {
        CP_WAIT(1);
        __syncthreads();
        if (it + 2 < NK) LOAD_TILE((it + 2) % STAGES, it + 2);
        CP_COMMIT();

        uint32_t sA = sb + (it % STAGES) * STAGE_BYTES;
        uint32_t sB = sA + 16384;

        #pragma unroll
        for (int kk = 0; kk < 4; kk++) {
            const int ch = kk * 2 + (l >> 4);   // 16B chunk index along k
            uint32_t a[2][4];
            #pragma unroll
            for (int mf = 0; mf < 2; mf++) {
                int row = wm + mf * 16 + (l & 15);
                uint32_t off = row * 128 + ((ch ^ (row & 7)) * 16);
                LDSM_X4(a[mf][0], a[mf][1], a[mf][2], a[mf][3], sA + off);
            }
            uint32_t bf[8][2];
            #pragma unroll
            for (int nb = 0; nb < 4; nb++) {
                int row = wn + nb * 16 + (l & 15);
                uint32_t off = row * 128 + ((ch ^ (row & 7)) * 16);
                uint32_t r0, r1, r2, r3;
                LDSM_X4(r0, r1, r2, r3, sB + off);
                bf[2 * nb][0] = r0; bf[2 * nb][1] = r2;
                bf[2 * nb + 1][0] = r1; bf[2 * nb + 1][1] = r3;
            }
            #pragma unroll
            for (int mf = 0; mf < 2; mf++)
                #pragma unroll
                for (int nf = 0; nf < 8; nf++)
                    MMA16816(acc[mf][nf], a[mf], bf[nf]);
        }
    }

    // ---- epilogue: cosine normalization + mask, straight from registers ----
    #pragma unroll
    for (int mf = 0; mf < 2; mf++) {
        #pragma unroll
        for (int half = 0; half < 2; half++) {
            const int m = bm + wm + mf * 16 + (l >> 2) + half * 8;
            const float invq = g_inv_qn[b * SQ + m];
            float* orow = out + ((size_t)b * SQ + m) * SK + bn;
            #pragma unroll
            for (int nf = 0; nf < 8; nf++) {
                const int nl = wn + nf * 8 + (l & 3) * 2;
                const float kk0 = s_kk[nl];
                const float kk1 = s_kk[nl + 1];
                const float v0 = acc[mf][nf][half * 2 + 0];
                const float v1 = acc[mf][nf][half * 2 + 1];
                float2 o;
                o.x = (kk0 == 0.0f) ? NEGV : v0 * invq * kk0;
                o.y = (kk1 == 0.0f) ? NEGV : v1 * invq * kk1;
                *(float2*)(orow + nl) = o;
            }
        }
    }
}

// ---------------------------------------------------------------------------
extern "C" void kernel_launch(void* const* d_in, const int* in_sizes, int n_in,
                              void* d_out, int out_size) {
    const float* q = (const float*)d_in[0];
    const float* k = (const float*)d_in[1];
    const int* mask = (const int*)d_in[2];
    float* out = (float*)d_out;

    cudaFuncSetAttribute(gemm_mma_kernel,
                         cudaFuncAttributeMaxDynamicSharedMemorySize, SMEM_TOTAL);

    prep_kernel<<<B_ * SQ + B_ * SK, 256>>>(q, k);

    dim3 grid(SK / 128, SQ / 128, B_);
    gemm_mma_kernel<<<grid, 256, SMEM_TOTAL>>>(mask, out);
}